// round 11
// baseline (speedup 1.0000x reference)
#include <cuda_runtime.h>
#include <math.h>

#define BB 64
#define TT 26
#define EE 300
#define HH 1024
#define G4 4096
#define FEATN 2048
#define SS 49
#define D1N 245000
#define D2N 5000
#define MON 1000
#define VOCABN 3000
#define QDIM 2048
#define IDIM 4096
#define IQN (MON*SS)

// conv1 tiling: 10 bins, 65-m tiles, 64-lane mapping + padded bins
#define BIN1 24500
#define NBINS 10
#define MTILE 65
#define CTHREADS 640
#define WSZ 41504
#define JPAD 2080
#define CONV_SMEM (WSZ*4 + JPAD*4 + JPAD*4)

// LSTM fused GEMM tiling
#define NZ 8               // K-split
#define NCT 32             // column tiles of 128

// ---------------- scratch (device globals) ----------------
__device__ float g_xW[TT*BB*G4];
__device__ float g_gates[NZ*BB*G4];
__device__ float g_c[BB*HH];
__device__ float g_hs[TT*BB*HH];
__device__ int   g_cnt[NCT];
__device__ float g_qa1[TT*BB*512];
__device__ float g_qa2[BB*2*TT];
__device__ float g_qatt[BB*2*TT];
__device__ float g_qfeat[BB*QDIM];
__device__ float g_qv1[BB*QDIM];
__device__ float g_qv2[BB*QDIM];
__device__ float g_qp1[BB*JPAD];
__device__ float g_csx[BB*D1N];
__device__ float g_P1[BB*D1N];
__device__ float g_iq[BB*IQN];
__device__ float g_nrm1[BB];
__device__ float g_iqn[BB*IQN];
__device__ float g_ia1[BB*SS*512];
__device__ float g_ia2[BB*2*SS];
__device__ float g_iatt[BB*2*SS];
__device__ float g_ifeat[BB*IDIM];
__device__ float g_z2n[BB*MON];
__device__ float g_logits[BB*VOCABN];
__device__ int   g_binoff[NBINS+1];
__device__ int   g_perm[JPAD];
__device__ int   g_hperm[JPAD];

__device__ __forceinline__ float sigmoidf_(float x) { return 1.f / (1.f + expf(-x)); }

// ---------------- init ----------------
__global__ void init_state_k() {
    int i = blockIdx.x * 256 + threadIdx.x;
    if (i < BB * HH) g_c[i] = 0.f;
    if (i < NCT) g_cnt[i] = 0;
    if (i < BB) g_nrm1[i] = 0.f;
}
__global__ void zero_csx_k() {
    int i = blockIdx.x * 256 + threadIdx.x;
    if (i < BB * D1N) g_csx[i] = 0.f;
}

// ---------------- bin h1q (bins padded to multiples of 4) ----------------
__global__ void bin_h_k(const int* __restrict__ h1q) {
    __shared__ int cnt[NBINS];
    __shared__ int start[NBINS+1];
    __shared__ int ofs[NBINS];
    int tid = threadIdx.x;
    if (tid < NBINS) cnt[tid] = 0;
    __syncthreads();
    for (int j = tid; j < QDIM; j += 256) atomicAdd(&cnt[h1q[j] / BIN1], 1);
    __syncthreads();
    if (tid == 0) {
        int s = 0;
        for (int k = 0; k < NBINS; k++) {
            start[k] = s; ofs[k] = s;
            g_binoff[k] = s;
            s += (cnt[k] + 3) & ~3;
        }
        start[NBINS] = s;
        g_binoff[NBINS] = s;
    }
    __syncthreads();
    for (int i = tid; i < JPAD; i += 256) { g_perm[i] = -1; g_hperm[i] = 0; }
    __syncthreads();
    for (int k = 0; k < NBINS; k++)
        for (int i = start[k] + tid; i < start[k+1]; i += 256)
            g_hperm[i] = k * BIN1;
    __syncthreads();
    for (int j = tid; j < QDIM; j += 256) {
        int h = h1q[j];
        int p = atomicAdd(&ofs[h / BIN1], 1);
        g_perm[p] = j;
        g_hperm[p] = h;
    }
}

__global__ void permq_k() {
    int b = blockIdx.x;
    for (int i = threadIdx.x; i < JPAD; i += 256) {
        int p = g_perm[i];
        g_qp1[b * JPAD + i] = (p >= 0) ? g_qv1[b * QDIM + p] : 0.f;
    }
}

// ---------------- generic tiled SGEMM ----------------
__global__ void sgemm(const float* __restrict__ A, const float* __restrict__ W,
                      const float* __restrict__ bias1, const float* __restrict__ bias2,
                      float* __restrict__ C,
                      int M, int N, int K, int RD, int S1, int S2, int kstride, int relu)
{
    __shared__ float As[16][64];
    __shared__ float Bs[16][64];
    const int bn = blockIdx.x * 64;
    const int bm = blockIdx.y * 64;
    const int tid = threadIdx.x;
    const int tm = (tid / 16) * 4;
    const int tn = (tid % 16) * 4;

    int kPer = (K + gridDim.z - 1) / gridDim.z;
    int kBeg = blockIdx.z * kPer;
    int kEnd = min(K, kBeg + kPer);

    float acc[4][4];
#pragma unroll
    for (int i = 0; i < 4; i++)
#pragma unroll
        for (int j = 0; j < 4; j++) acc[i][j] = 0.f;

    const int lm = tid >> 2;
    const int lk = (tid & 3) << 2;

    for (int k0 = kBeg; k0 < kEnd; k0 += 16) {
        {
            int row = bm + lm;
            float va[4] = {0.f, 0.f, 0.f, 0.f};
            if (row < M) {
                size_t base = (size_t)(row / RD) * S1 + (size_t)(row % RD) * S2;
                int kg = k0 + lk;
#pragma unroll
                for (int i = 0; i < 4; i++)
                    if (kg + i < kEnd) va[i] = A[base + (size_t)(kg + i) * kstride];
            }
#pragma unroll
            for (int i = 0; i < 4; i++) As[lk + i][lm] = va[i];
        }
        {
            int col = bn + lm;
            float vb[4] = {0.f, 0.f, 0.f, 0.f};
            if (col < N) {
                int kg = k0 + lk;
#pragma unroll
                for (int i = 0; i < 4; i++)
                    if (kg + i < kEnd) vb[i] = W[(size_t)col * K + kg + i];
            }
#pragma unroll
            for (int i = 0; i < 4; i++) Bs[lk + i][lm] = vb[i];
        }
        __syncthreads();
#pragma unroll
        for (int k = 0; k < 16; k++) {
            float4 av = *(const float4*)&As[k][tm];
            float4 bv = *(const float4*)&Bs[k][tn];
            float a4[4] = {av.x, av.y, av.z, av.w};
            float b4[4] = {bv.x, bv.y, bv.z, bv.w};
#pragma unroll
            for (int i = 0; i < 4; i++)
#pragma unroll
                for (int j = 0; j < 4; j++) acc[i][j] += a4[i] * b4[j];
        }
        __syncthreads();
    }

    float* Cz = C + (size_t)blockIdx.z * M * N;
#pragma unroll
    for (int i = 0; i < 4; i++) {
        int row = bm + tm + i;
        if (row >= M) continue;
#pragma unroll
        for (int j = 0; j < 4; j++) {
            int col = bn + tn + j;
            if (col >= N) continue;
            float v = acc[i][j];
            if (blockIdx.z == 0) {
                if (bias1) v += bias1[col];
                if (bias2) v += bias2[col];
            }
            if (relu) v = fmaxf(v, 0.f);
            Cz[(size_t)row * N + col] = v;
        }
    }
}

// ---------------- fused LSTM step: 64x128 tile, 4x8 per thread ----------------
// grid (NCT=32 ctiles, NZ=8 k-slices), 256 threads. Columns interleaved c = h*4+g.
__global__ __launch_bounds__(256) void lstm_fused(const float* __restrict__ W_hh, int t) {
    __shared__ float As[16][64];
    __shared__ float Bs[16][128];
    __shared__ int s_last;
    const int ct = blockIdx.x;
    const int z = blockIdx.y;
    const int bn = ct * 128;
    const int tid = threadIdx.x;
    const int tm = (tid / 16) * 4;
    const int tn = (tid % 16) * 8;

    float acc[4][8];
#pragma unroll
    for (int i = 0; i < 4; i++)
#pragma unroll
        for (int j = 0; j < 8; j++) acc[i][j] = 0.f;

    if (t > 0) {
        const float* hprev = g_hs + (size_t)(t - 1) * BB * HH;
        const int lmA = tid >> 2;            // row 0..63
        const int lkA = (tid & 3) << 2;      // k offset 0,4,8,12
        const int lmB = tid >> 1;            // col 0..127
        const int lkB = (tid & 1) << 3;      // k offset 0 or 8
        int kBeg = z * (HH / NZ);            // 128 per slice
        for (int k0 = kBeg; k0 < kBeg + HH / NZ; k0 += 16) {
            {
                float4 va = *(const float4*)&hprev[lmA * HH + k0 + lkA];
                As[lkA + 0][lmA] = va.x; As[lkA + 1][lmA] = va.y;
                As[lkA + 2][lmA] = va.z; As[lkA + 3][lmA] = va.w;
            }
            {
                int col = bn + lmB;
                int r = (col & 3) * HH + (col >> 2);
                const float* wr = &W_hh[(size_t)r * HH + k0 + lkB];
                float4 vb0 = *(const float4*)wr;
                float4 vb1 = *(const float4*)(wr + 4);
                Bs[lkB + 0][lmB] = vb0.x; Bs[lkB + 1][lmB] = vb0.y;
                Bs[lkB + 2][lmB] = vb0.z; Bs[lkB + 3][lmB] = vb0.w;
                Bs[lkB + 4][lmB] = vb1.x; Bs[lkB + 5][lmB] = vb1.y;
                Bs[lkB + 6][lmB] = vb1.z; Bs[lkB + 7][lmB] = vb1.w;
            }
            __syncthreads();
#pragma unroll
            for (int k = 0; k < 16; k++) {
                float4 av = *(const float4*)&As[k][tm];
                float4 bv0 = *(const float4*)&Bs[k][tn];
                float4 bv1 = *(const float4*)&Bs[k][tn + 4];
                float a4[4] = {av.x, av.y, av.z, av.w};
                float b8[8] = {bv0.x, bv0.y, bv0.z, bv0.w, bv1.x, bv1.y, bv1.z, bv1.w};
#pragma unroll
                for (int i = 0; i < 4; i++)
#pragma unroll
                    for (int j = 0; j < 8; j++) acc[i][j] += a4[i] * b8[j];
            }
            __syncthreads();
        }
    }

    // write partials
    float* Pz = g_gates + (size_t)z * BB * G4;
#pragma unroll
    for (int i = 0; i < 4; i++)
#pragma unroll
        for (int j = 0; j < 8; j++)
            Pz[(size_t)(tm + i) * G4 + bn + tn + j] = acc[i][j];

    __threadfence();
    __syncthreads();
    if (tid == 0) {
        int d = atomicAdd(&g_cnt[ct], 1);
        s_last = (d == NZ - 1) ? 1 : 0;
    }
    __syncthreads();
    if (!s_last) return;
    __threadfence();
    if (tid == 0) g_cnt[ct] = 0;

    // epilogue: 64 batches x 32 h-units (2048 items)
#pragma unroll
    for (int i = 0; i < 8; i++) {
        int idx = tid + 256 * i;
        int b = idx >> 5;
        int hl = idx & 31;
        int h = ct * 32 + hl;
        const float* xw = g_xW + (size_t)(t * BB + b) * G4;
        float gv[4];
#pragma unroll
        for (int g = 0; g < 4; g++) {
            int c = bn + hl * 4 + g;
            float s = 0.f;
#pragma unroll
            for (int zz = 0; zz < NZ; zz++)
                s += __ldcg(&g_gates[(size_t)zz * BB * G4 + (size_t)b * G4 + c]);
            gv[g] = s + xw[g * HH + h];
        }
        int id = b * HH + h;
        float cn = sigmoidf_(gv[1]) * g_c[id] + sigmoidf_(gv[0]) * tanhf(gv[2]);
        float hn = sigmoidf_(gv[3]) * tanhf(cn);
        g_c[id] = cn;
        g_hs[(size_t)t * BB * HH + id] = hn;
    }
}

// ---------------- 2-channel 1x1 conv (512 -> 2) ----------------
__global__ void att2_k(const float* __restrict__ X, const float* __restrict__ W2,
                       const float* __restrict__ b2, float* __restrict__ out,
                       int L, int bdiv) {
    int r = blockIdx.x;
    const float* a = X + (size_t)r * 512;
    float s0 = 0.f, s1 = 0.f;
    for (int o = threadIdx.x; o < 512; o += 128) {
        float v = a[o];
        s0 += W2[o] * v; s1 += W2[512 + o] * v;
    }
    __shared__ float r0[128], r1[128];
    r0[threadIdx.x] = s0; r1[threadIdx.x] = s1; __syncthreads();
    for (int st = 64; st > 0; st >>= 1) {
        if (threadIdx.x < st) { r0[threadIdx.x] += r0[threadIdx.x + st]; r1[threadIdx.x] += r1[threadIdx.x + st]; }
        __syncthreads();
    }
    if (threadIdx.x == 0) {
        int b, l;
        if (bdiv == 0) { b = r & 63; l = r >> 6; }
        else { b = r / 49; l = r % 49; }
        out[(b * 2 + 0) * L + l] = r0[0] + b2[0];
        out[(b * 2 + 1) * L + l] = r1[0] + b2[1];
    }
}

// ---------------- small row softmax (n <= 64), 64 threads ----------------
__global__ void softmax_small(const float* __restrict__ in, float* __restrict__ out, int n) {
    __shared__ float sm[64];
    int r = blockIdx.x, tid = threadIdx.x;
    float v = (tid < n) ? in[(size_t)r * n + tid] : -1e30f;
    sm[tid] = v; __syncthreads();
    for (int st = 32; st > 0; st >>= 1) {
        if (tid < st) sm[tid] = fmaxf(sm[tid], sm[tid + st]);
        __syncthreads();
    }
    float mx = sm[0]; __syncthreads();
    float e = (tid < n) ? expf(v - mx) : 0.f;
    sm[tid] = e; __syncthreads();
    for (int st = 32; st > 0; st >>= 1) {
        if (tid < st) sm[tid] += sm[tid + st];
        __syncthreads();
    }
    if (tid < n) out[(size_t)r * n + tid] = e / sm[0];
}

// ---------------- question feature + signed copies ----------------
__global__ void qfeat_k(const int* __restrict__ s1q, const int* __restrict__ s2q) {
    int b = blockIdx.x, g = blockIdx.y;
    __shared__ float att[TT];
    if (threadIdx.x < TT) att[threadIdx.x] = g_qatt[(b * 2 + g) * TT + threadIdx.x];
    __syncthreads();
    for (int h = threadIdx.x; h < HH; h += blockDim.x) {
        float acc = 0.f;
        for (int t = 0; t < TT; t++)
            acc += att[t] * g_hs[((size_t)t * BB + b) * HH + h];
        int j = g * HH + h;
        g_qfeat[b * QDIM + j] = acc;
        g_qv1[b * QDIM + j] = acc * (float)(2 * s1q[j] - 1);
        g_qv2[b * QDIM + j] = acc * (float)(2 * s2q[j] - 1);
    }
}

// ---------------- MCB1: scatter, pool ----------------
__global__ void scatter1(const float* __restrict__ img, const int* __restrict__ h1x,
                         const int* __restrict__ s1x) {
    int id = blockIdx.x * 256 + threadIdx.x;
    if (id >= BB * SS * FEATN) return;
    int f = id % FEATN;
    int r = id / FEATN;
    int s = r % SS, b = r / SS;
    int n = f * SS + s;
    float v = img[id] * (float)(2 * s1x[n] - 1);
    atomicAdd(&g_csx[(size_t)b * D1N + h1x[n]], v);
}

__global__ void pool1() {
    int id = blockIdx.x * 256 + threadIdx.x;
    if (id >= BB * D1N) return;
    int t = id % D1N; int b = id / D1N;
    const float* cs = g_csx + (size_t)b * D1N;
    float a = 0.f;
#pragma unroll
    for (int f = 0; f < 5; f++) {
        int tt = t + 49 * f;
        if (tt >= D1N) tt -= D1N;
        a += cs[tt];
    }
    g_P1[id] = a;
}

// ---------------- MCB1 conv: smem window, j-quad inner, fused |x| partial ----------------
__global__ void conv1_k() {
    extern __shared__ float smw[];
    float* win = smw;                    // [WSZ]
    float* sq  = smw + WSZ;              // [JPAD]
    int*   sh  = (int*)(sq + JPAD);      // [JPAD]
    int b = blockIdx.y;
    int m0 = blockIdx.x * MTILE;
    int tid = threadIdx.x;

    for (int i = tid; i < JPAD; i += CTHREADS) {
        sq[i] = g_qp1[b * JPAD + i];
        sh[i] = g_hperm[i];
    }

    int mg = tid >> 6;
    int sl = tid & 63;
    bool lane_ok = sl < 49;
    int offb = 245 * mg + sl;
    float acc[7] = {0.f, 0.f, 0.f, 0.f, 0.f, 0.f, 0.f};
    const float* Pb = g_P1 + (size_t)b * D1N;
    int T0 = 245 * m0;

    for (int k = 0; k < NBINS; k++) {
        __syncthreads();
        int W0 = T0 - (k + 1) * BIN1 + 1;
        W0 %= D1N; if (W0 < 0) W0 += D1N;
        for (int i = tid; i < WSZ; i += CTHREADS) {
            int g = W0 + i; if (g >= D1N) g -= D1N;
            win[i] = Pb[g];
        }
        __syncthreads();
        int j0 = g_binoff[k], j1 = g_binoff[k + 1];
        if (lane_ok) {
            int base0 = (k + 1) * BIN1 - 1 + offb;
            for (int j = j0; j < j1; j += 4) {
                float4 q4 = *(const float4*)&sq[j];
                int4   h4 = *(const int4*)&sh[j];
                {
                    int a = base0 - h4.x; float q = q4.x;
#pragma unroll
                    for (int it = 0; it < 7; it++) acc[it] += q * win[a + 2450 * it];
                }
                {
                    int a = base0 - h4.y; float q = q4.y;
#pragma unroll
                    for (int it = 0; it < 7; it++) acc[it] += q * win[a + 2450 * it];
                }
                {
                    int a = base0 - h4.z; float q = q4.z;
#pragma unroll
                    for (int it = 0; it < 7; it++) acc[it] += q * win[a + 2450 * it];
                }
                {
                    int a = base0 - h4.w; float q = q4.w;
#pragma unroll
                    for (int it = 0; it < 7; it++) acc[it] += q * win[a + 2450 * it];
                }
            }
        }
    }

    // write + fused |x| partial for the L2 norm (||signed_sqrt(x)||^2 = sum|x|)
    float part = 0.f;
    if (lane_ok) {
#pragma unroll
        for (int it = 0; it < 7; it++) {
            int m = mg + 10 * it;
            if (m < MTILE && m0 + m < MON) {
                g_iq[(size_t)b * IQN + (m0 + m) * 49 + sl] = acc[it];
                part += fabsf(acc[it]);
            }
        }
    }
    __syncthreads();
    sq[tid] = part;
    __syncthreads();
    for (int st = 512; st > 0; st >>= 1) {
        if (tid < st && tid + st < CTHREADS) sq[tid] += sq[tid + st];
        __syncthreads();
    }
    if (tid == 0) atomicAdd(&g_nrm1[b], sq[0]);
}

__global__ void scale1_k() {
    int id = blockIdx.x * 256 + threadIdx.x;
    if (id >= BB * IQN) return;
    int b = id / IQN;
    float inv = 1.f / fmaxf(sqrtf(g_nrm1[b]), 1e-12f);
    float x = g_iq[id];
    g_iqn[id] = copysignf(sqrtf(fabsf(x)), x) * inv;
}

// ---------------- image feature ----------------
__global__ void ifeat_k(const float* __restrict__ img) {
    int b = blockIdx.x;
    __shared__ float a0[SS], a1[SS];
    if (threadIdx.x < SS) {
        a0[threadIdx.x] = g_iatt[(b * 2 + 0) * SS + threadIdx.x];
        a1[threadIdx.x] = g_iatt[(b * 2 + 1) * SS + threadIdx.x];
    }
    __syncthreads();
    int f = blockIdx.y * 256 + threadIdx.x;
    float acc0 = 0.f, acc1 = 0.f;
    for (int s = 0; s < SS; s++) {
        float v = img[((size_t)b * SS + s) * FEATN + f];
        acc0 += a0[s] * v; acc1 += a1[s] * v;
    }
    g_ifeat[b * IDIM + f] = acc0;
    g_ifeat[b * IDIM + FEATN + f] = acc1;
}

// ---------------- MCB2 fully fused ----------------
__global__ void mcb2_k(const int* __restrict__ h2i, const int* __restrict__ s2i,
                       const int* __restrict__ h2q) {
    __shared__ float cs[D2N];
    __shared__ float sq[QDIM];
    __shared__ int   shh[QDIM];
    __shared__ float red[256];
    int b = blockIdx.x, tid = threadIdx.x;
    for (int i = tid; i < D2N; i += 256) cs[i] = 0.f;
    for (int j = tid; j < QDIM; j += 256) { sq[j] = g_qv2[b * QDIM + j]; shh[j] = h2q[j]; }
    __syncthreads();
    for (int n = tid; n < IDIM; n += 256) {
        float v = g_ifeat[b * IDIM + n] * (float)(2 * s2i[n] - 1);
        atomicAdd(&cs[h2i[n]], v);
    }
    __syncthreads();
    float p[20];
#pragma unroll
    for (int k = 0; k < 20; k++) {
        int t = tid + k * 256;
        float a = 0.f;
        if (t < D2N) {
#pragma unroll
            for (int f = 0; f < 5; f++) { int u = t + f; if (u >= D2N) u -= D2N; a += cs[u]; }
        }
        p[k] = a;
    }
    __syncthreads();
#pragma unroll
    for (int k = 0; k < 20; k++) { int t = tid + k * 256; if (t < D2N) cs[t] = p[k]; }
    __syncthreads();
    float z[4] = {0.f, 0.f, 0.f, 0.f};
    int mb[4];
#pragma unroll
    for (int k = 0; k < 4; k++) { int m = tid + k * 256; mb[k] = (m < MON) ? 5 * m : 0; }
    for (int j = 0; j < QDIM; j++) {
        int h = shh[j]; float q = sq[j];
#pragma unroll
        for (int k = 0; k < 4; k++) { int d = mb[k] - h; if (d < 0) d += D2N; z[k] += q * cs[d]; }
    }
    float sa = 0.f;
#pragma unroll
    for (int k = 0; k < 4; k++) { if (tid + k * 256 < MON) sa += fabsf(z[k]); }
    red[tid] = sa; __syncthreads();
    for (int st = 128; st > 0; st >>= 1) {
        if (tid < st) red[tid] += red[tid + st];
        __syncthreads();
    }
    float inv = 1.f / fmaxf(sqrtf(red[0]), 1e-12f);
#pragma unroll
    for (int k = 0; k < 4; k++) {
        int m = tid + k * 256;
        if (m < MON) g_z2n[b * MON + m] = copysignf(sqrtf(fabsf(z[k])), z[k]) * inv;
    }
}

// ---------------- final softmax (3000) ----------------
__global__ void softmax_out(float* __restrict__ out) {
    int b = blockIdx.x, tid = threadIdx.x;
    __shared__ float red[256];
    const float* lg = g_logits + (size_t)b * VOCABN;
    float mx = -1e30f;
    for (int i = tid; i < VOCABN; i += 256) mx = fmaxf(mx, lg[i]);
    red[tid] = mx; __syncthreads();
    for (int st = 128; st > 0; st >>= 1) {
        if (tid < st) red[tid] = fmaxf(red[tid], red[tid + st]);
        __syncthreads();
    }
    mx = red[0]; __syncthreads();
    float s = 0.f;
    for (int i = tid; i < VOCABN; i += 256) s += expf(lg[i] - mx);
    red[tid] = s; __syncthreads();
    for (int st = 128; st > 0; st >>= 1) {
        if (tid < st) red[tid] += red[tid + st];
        __syncthreads();
    }
    float inv = 1.f / red[0];
    for (int i = tid; i < VOCABN; i += 256) out[(size_t)b * VOCABN + i] = expf(lg[i] - mx) * inv;
}

// ---------------- host launcher ----------------
static float* sym(const void* s) {
    void* p = nullptr;
    cudaGetSymbolAddress(&p, s);
    return (float*)p;
}

extern "C" void kernel_launch(void* const* d_in, const int* in_sizes, int n_in,
                              void* d_out, int out_size) {
    const float* ques  = (const float*)d_in[0];
    const float* img   = (const float*)d_in[1];
    const float* W_ih  = (const float*)d_in[2];
    const float* W_hh  = (const float*)d_in[3];
    const float* b_ih  = (const float*)d_in[4];
    const float* b_hh  = (const float*)d_in[5];
    const float* Wq1   = (const float*)d_in[6];
    const float* bq1   = (const float*)d_in[7];
    const float* Wq2   = (const float*)d_in[8];
    const float* bq2   = (const float*)d_in[9];
    const float* Wi1   = (const float*)d_in[10];
    const float* bi1   = (const float*)d_in[11];
    const float* Wi2   = (const float*)d_in[12];
    const float* bi2   = (const float*)d_in[13];
    const float* Wp    = (const float*)d_in[14];
    const float* bp    = (const float*)d_in[15];
    const int* h1x = (const int*)d_in[16];
    const int* s1x = (const int*)d_in[17];
    const int* h1q = (const int*)d_in[18];
    const int* s1q = (const int*)d_in[19];
    const int* h2i = (const int*)d_in[20];
    const int* s2i = (const int*)d_in[21];
    const int* h2q = (const int*)d_in[22];
    const int* s2q = (const int*)d_in[23];
    float* out = (float*)d_out;

    float* p_xW    = sym(g_xW);
    float* p_hs    = sym(g_hs);
    float* p_qa1   = sym(g_qa1);
    float* p_qa2   = sym(g_qa2);
    float* p_qatt  = sym(g_qatt);
    float* p_ia1   = sym(g_ia1);
    float* p_ia2   = sym(g_ia2);
    float* p_iatt  = sym(g_iatt);
    float* p_iqn   = sym(g_iqn);
    float* p_z2n   = sym(g_z2n);
    float* p_logits= sym(g_logits);

    cudaFuncSetAttribute(conv1_k, cudaFuncAttributeMaxDynamicSharedMemorySize, CONV_SMEM);

    cudaStream_t side;
    cudaStreamCreateWithFlags(&side, cudaStreamNonBlocking);
    cudaEvent_t e_fork, e_join;
    cudaEventCreateWithFlags(&e_fork, cudaEventDisableTiming);
    cudaEventCreateWithFlags(&e_join, cudaEventDisableTiming);

    // main-stream init needed by both branches
    init_state_k<<<(BB*HH + 255)/256, 256>>>();
    bin_h_k<<<1, 256>>>(h1q);

    // fork: img-side preprocessing on side stream
    cudaEventRecord(e_fork, 0);
    cudaStreamWaitEvent(side, e_fork, 0);
    zero_csx_k<<<(BB*D1N + 255)/256, 256, 0, side>>>();
    scatter1<<<(BB*SS*FEATN + 255)/256, 256, 0, side>>>(img, h1x, s1x);
    pool1<<<(BB*D1N + 255)/256, 256, 0, side>>>();
    cudaEventRecord(e_join, side);

    // main stream: xW GEMM + LSTM chain
    {
        dim3 g(G4/64, (TT*BB + 63)/64, 1);
        sgemm<<<g, 256>>>(ques, W_ih, b_ih, b_hh, p_xW,
                          TT*BB, G4, EE, BB, EE, TT*EE, 1, 0);
    }
    for (int t = 0; t < TT; t++) {
        dim3 g(NCT, NZ, 1);
        lstm_fused<<<g, 256>>>(W_hh, t);
    }

    // question attention
    {
        dim3 g(512/64, (TT*BB + 63)/64, 1);
        sgemm<<<g, 256>>>(p_hs, Wq1, bq1, nullptr, p_qa1,
                          TT*BB, 512, HH, 1, HH, 0, 1, 1);
    }
    att2_k<<<TT*BB, 128>>>(p_qa1, Wq2, bq2, p_qa2, TT, 0);
    softmax_small<<<BB*2, 64>>>(p_qa2, p_qatt, TT);
    {
        dim3 g(BB, 2);
        qfeat_k<<<g, 256>>>(s1q, s2q);
    }
    permq_k<<<BB, 256>>>();

    // join: conv1 needs pool1 (side) + permq (main)
    cudaStreamWaitEvent(0, e_join, 0);

    // MCB1 conv (fused norm partial) + scale
    {
        dim3 g((MON + MTILE - 1)/MTILE, BB);
        conv1_k<<<g, CTHREADS, CONV_SMEM>>>();
    }
    scale1_k<<<(BB*IQN + 255)/256, 256>>>();

    // image attention
    {
        dim3 g(512/64, (BB*SS + 63)/64, 1);
        sgemm<<<g, 256>>>(p_iqn, Wi1, bi1, nullptr, p_ia1,
                          BB*SS, 512, MON, SS, IQN, 1, SS, 1);
    }
    att2_k<<<BB*SS, 128>>>(p_ia1, Wi2, bi2, p_ia2, SS, 1);
    softmax_small<<<BB*2, 64>>>(p_ia2, p_iatt, SS);
    {
        dim3 g(BB, FEATN/256);
        ifeat_k<<<g, 256>>>(img);
    }

    // MCB2 fused
    mcb2_k<<<BB, 256>>>(h2i, s2i, h2q);

    // classifier + softmax
    {
        dim3 g((VOCABN + 63)/64, 1, 1);
        sgemm<<<g, 256>>>(p_z2n, Wp, bp, nullptr, p_logits,
                          BB, VOCABN, MON, 1, MON, 0, 1, 0);
    }
    softmax_out<<<BB, 256>>>(out);
}

// round 14
// speedup vs baseline: 1.0925x; 1.0925x over previous
#include <cuda_runtime.h>
#include <math.h>

#define BB 64
#define TT 26
#define EE 300
#define HH 1024
#define G4 4096
#define FEATN 2048
#define SS 49
#define D1N 245000
#define D2N 5000
#define MON 1000
#define VOCABN 3000
#define QDIM 2048
#define IDIM 4096
#define IQN (MON*SS)

// conv1 tiling: 10 bins, 65-m tiles, 64-lane mapping + padded bins
#define BIN1 24500
#define NBINS 10
#define MTILE 65
#define CTHREADS 640
#define WSZ 41504
#define JPAD 2080
#define CONV_SMEM (WSZ*4 + JPAD*4 + JPAD*4)

// ---------------- scratch (device globals) ----------------
__device__ float g_xW[TT*BB*G4];
__device__ float g_gates[4*BB*G4];
__device__ float g_c[BB*HH];
__device__ float g_hs[TT*BB*HH];
__device__ int   g_cnt[64];
__device__ float g_qa1[TT*BB*512];
__device__ float g_qa2[BB*2*TT];
__device__ float g_qatt[BB*2*TT];
__device__ float g_qfeat[BB*QDIM];
__device__ float g_qv1[BB*QDIM];
__device__ float g_qv2[BB*QDIM];
__device__ float g_qp1[BB*JPAD];
__device__ float g_csx[BB*D1N];
__device__ float g_P1[BB*D1N];
__device__ float g_iq[BB*IQN];
__device__ float g_nrm1[BB];
__device__ float g_iqn[BB*IQN];
__device__ float g_ia1[BB*SS*512];
__device__ float g_ia2[BB*2*SS];
__device__ float g_iatt[BB*2*SS];
__device__ float g_ifeat[BB*IDIM];
__device__ float g_z2n[BB*MON];
__device__ float g_logits[BB*VOCABN];
__device__ int   g_binoff[NBINS+1];
__device__ int   g_perm[JPAD];
__device__ int   g_hperm[JPAD];

__device__ __forceinline__ float sigmoidf_(float x) { return 1.f / (1.f + expf(-x)); }

// ---------------- init ----------------
__global__ void init_state_k() {
    int i = blockIdx.x * 256 + threadIdx.x;
    if (i < BB * HH) g_c[i] = 0.f;
    if (i < 64) g_cnt[i] = 0;
    if (i < BB) g_nrm1[i] = 0.f;
}
__global__ void zero_csx_k() {
    int i = blockIdx.x * 256 + threadIdx.x;
    if (i < BB * D1N) g_csx[i] = 0.f;
}

// ---------------- bin h1q (bins padded to multiples of 4) ----------------
__global__ void bin_h_k(const int* __restrict__ h1q) {
    __shared__ int cnt[NBINS];
    __shared__ int start[NBINS+1];
    __shared__ int ofs[NBINS];
    int tid = threadIdx.x;
    if (tid < NBINS) cnt[tid] = 0;
    __syncthreads();
    for (int j = tid; j < QDIM; j += 256) atomicAdd(&cnt[h1q[j] / BIN1], 1);
    __syncthreads();
    if (tid == 0) {
        int s = 0;
        for (int k = 0; k < NBINS; k++) {
            start[k] = s; ofs[k] = s;
            g_binoff[k] = s;
            s += (cnt[k] + 3) & ~3;
        }
        start[NBINS] = s;
        g_binoff[NBINS] = s;
    }
    __syncthreads();
    for (int i = tid; i < JPAD; i += 256) { g_perm[i] = -1; g_hperm[i] = 0; }
    __syncthreads();
    for (int k = 0; k < NBINS; k++)
        for (int i = start[k] + tid; i < start[k+1]; i += 256)
            g_hperm[i] = k * BIN1;
    __syncthreads();
    for (int j = tid; j < QDIM; j += 256) {
        int h = h1q[j];
        int p = atomicAdd(&ofs[h / BIN1], 1);
        g_perm[p] = j;
        g_hperm[p] = h;
    }
}

__global__ void permq_k() {
    int b = blockIdx.x;
    for (int i = threadIdx.x; i < JPAD; i += 256) {
        int p = g_perm[i];
        g_qp1[b * JPAD + i] = (p >= 0) ? g_qv1[b * QDIM + p] : 0.f;
    }
}

// ---------------- generic tiled SGEMM ----------------
__global__ void sgemm(const float* __restrict__ A, const float* __restrict__ W,
                      const float* __restrict__ bias1, const float* __restrict__ bias2,
                      float* __restrict__ C,
                      int M, int N, int K, int RD, int S1, int S2, int kstride, int relu)
{
    __shared__ float As[16][64];
    __shared__ float Bs[16][64];
    const int bn = blockIdx.x * 64;
    const int bm = blockIdx.y * 64;
    const int tid = threadIdx.x;
    const int tm = (tid / 16) * 4;
    const int tn = (tid % 16) * 4;

    int kPer = (K + gridDim.z - 1) / gridDim.z;
    int kBeg = blockIdx.z * kPer;
    int kEnd = min(K, kBeg + kPer);

    float acc[4][4];
#pragma unroll
    for (int i = 0; i < 4; i++)
#pragma unroll
        for (int j = 0; j < 4; j++) acc[i][j] = 0.f;

    const int lm = tid >> 2;
    const int lk = (tid & 3) << 2;

    for (int k0 = kBeg; k0 < kEnd; k0 += 16) {
        {
            int row = bm + lm;
            float va[4] = {0.f, 0.f, 0.f, 0.f};
            if (row < M) {
                size_t base = (size_t)(row / RD) * S1 + (size_t)(row % RD) * S2;
                int kg = k0 + lk;
#pragma unroll
                for (int i = 0; i < 4; i++)
                    if (kg + i < kEnd) va[i] = A[base + (size_t)(kg + i) * kstride];
            }
#pragma unroll
            for (int i = 0; i < 4; i++) As[lk + i][lm] = va[i];
        }
        {
            int col = bn + lm;
            float vb[4] = {0.f, 0.f, 0.f, 0.f};
            if (col < N) {
                int kg = k0 + lk;
#pragma unroll
                for (int i = 0; i < 4; i++)
                    if (kg + i < kEnd) vb[i] = W[(size_t)col * K + kg + i];
            }
#pragma unroll
            for (int i = 0; i < 4; i++) Bs[lk + i][lm] = vb[i];
        }
        __syncthreads();
#pragma unroll
        for (int k = 0; k < 16; k++) {
            float4 av = *(const float4*)&As[k][tm];
            float4 bv = *(const float4*)&Bs[k][tn];
            float a4[4] = {av.x, av.y, av.z, av.w};
            float b4[4] = {bv.x, bv.y, bv.z, bv.w};
#pragma unroll
            for (int i = 0; i < 4; i++)
#pragma unroll
                for (int j = 0; j < 4; j++) acc[i][j] += a4[i] * b4[j];
        }
        __syncthreads();
    }

    float* Cz = C + (size_t)blockIdx.z * M * N;
#pragma unroll
    for (int i = 0; i < 4; i++) {
        int row = bm + tm + i;
        if (row >= M) continue;
#pragma unroll
        for (int j = 0; j < 4; j++) {
            int col = bn + tn + j;
            if (col >= N) continue;
            float v = acc[i][j];
            if (blockIdx.z == 0) {
                if (bias1) v += bias1[col];
                if (bias2) v += bias2[col];
            }
            if (relu) v = fmaxf(v, 0.f);
            Cz[(size_t)row * N + col] = v;
        }
    }
}

// ---------------- fused LSTM step (R9-proven: 64x64 tile, NZ=4) ----------------
__global__ __launch_bounds__(256) void lstm_fused(const float* __restrict__ W_hh, int t) {
    __shared__ float As[16][64];
    __shared__ float Bs[16][64];
    __shared__ int s_last;
    const int ct = blockIdx.x;
    const int z = blockIdx.y;
    const int bn = ct * 64;
    const int tid = threadIdx.x;
    const int tm = (tid / 16) * 4;
    const int tn = (tid % 16) * 4;

    float acc[4][4];
#pragma unroll
    for (int i = 0; i < 4; i++)
#pragma unroll
        for (int j = 0; j < 4; j++) acc[i][j] = 0.f;

    if (t > 0) {
        const float* hprev = g_hs + (size_t)(t - 1) * BB * HH;
        const int lm = tid >> 2;
        const int lk = (tid & 3) << 2;
        int kBeg = z * 256;
        for (int k0 = kBeg; k0 < kBeg + 256; k0 += 16) {
            {
                int kg = k0 + lk;
                float4 va = *(const float4*)&hprev[lm * HH + kg];
                As[lk + 0][lm] = va.x; As[lk + 1][lm] = va.y;
                As[lk + 2][lm] = va.z; As[lk + 3][lm] = va.w;
            }
            {
                int col = bn + lm;
                int r = (col & 3) * HH + (col >> 2);
                int kg = k0 + lk;
                float4 vb = *(const float4*)&W_hh[(size_t)r * HH + kg];
                Bs[lk + 0][lm] = vb.x; Bs[lk + 1][lm] = vb.y;
                Bs[lk + 2][lm] = vb.z; Bs[lk + 3][lm] = vb.w;
            }
            __syncthreads();
#pragma unroll
            for (int k = 0; k < 16; k++) {
                float4 av = *(const float4*)&As[k][tm];
                float4 bv = *(const float4*)&Bs[k][tn];
                float a4[4] = {av.x, av.y, av.z, av.w};
                float b4[4] = {bv.x, bv.y, bv.z, bv.w};
#pragma unroll
                for (int i = 0; i < 4; i++)
#pragma unroll
                    for (int j = 0; j < 4; j++) acc[i][j] += a4[i] * b4[j];
            }
            __syncthreads();
        }
    }

    float* Pz = g_gates + (size_t)z * BB * G4;
#pragma unroll
    for (int i = 0; i < 4; i++)
#pragma unroll
        for (int j = 0; j < 4; j++)
            Pz[(size_t)(tm + i) * G4 + bn + tn + j] = acc[i][j];

    __threadfence();
    __syncthreads();
    if (tid == 0) {
        int d = atomicAdd(&g_cnt[ct], 1);
        s_last = (d == 3) ? 1 : 0;
    }
    __syncthreads();
    if (!s_last) return;
    __threadfence();
    if (tid == 0) g_cnt[ct] = 0;

#pragma unroll
    for (int i = 0; i < 4; i++) {
        int idx = tid + 256 * i;
        int b = idx >> 4;
        int hl = idx & 15;
        int h = ct * 16 + hl;
        const float* xw = g_xW + (size_t)(t * BB + b) * G4;
        float gv[4];
#pragma unroll
        for (int g = 0; g < 4; g++) {
            int c = bn + hl * 4 + g;
            float s = __ldcg(&g_gates[(size_t)b * G4 + c])
                    + __ldcg(&g_gates[(size_t)(BB + b) * G4 + c])
                    + __ldcg(&g_gates[(size_t)(2 * BB + b) * G4 + c])
                    + __ldcg(&g_gates[(size_t)(3 * BB + b) * G4 + c]);
            gv[g] = s + xw[g * HH + h];
        }
        int id = b * HH + h;
        float cn = sigmoidf_(gv[1]) * g_c[id] + sigmoidf_(gv[0]) * tanhf(gv[2]);
        float hn = sigmoidf_(gv[3]) * tanhf(cn);
        g_c[id] = cn;
        g_hs[(size_t)t * BB * HH + id] = hn;
    }
}

// ---------------- 2-channel 1x1 conv (512 -> 2) ----------------
__global__ void att2_k(const float* __restrict__ X, const float* __restrict__ W2,
                       const float* __restrict__ b2, float* __restrict__ out,
                       int L, int bdiv) {
    int r = blockIdx.x;
    const float* a = X + (size_t)r * 512;
    float s0 = 0.f, s1 = 0.f;
    for (int o = threadIdx.x; o < 512; o += 128) {
        float v = a[o];
        s0 += W2[o] * v; s1 += W2[512 + o] * v;
    }
    __shared__ float r0[128], r1[128];
    r0[threadIdx.x] = s0; r1[threadIdx.x] = s1; __syncthreads();
    for (int st = 64; st > 0; st >>= 1) {
        if (threadIdx.x < st) { r0[threadIdx.x] += r0[threadIdx.x + st]; r1[threadIdx.x] += r1[threadIdx.x + st]; }
        __syncthreads();
    }
    if (threadIdx.x == 0) {
        int b, l;
        if (bdiv == 0) { b = r & 63; l = r >> 6; }
        else { b = r / 49; l = r % 49; }
        out[(b * 2 + 0) * L + l] = r0[0] + b2[0];
        out[(b * 2 + 1) * L + l] = r1[0] + b2[1];
    }
}

// ---------------- small row softmax (n <= 64), 64 threads ----------------
__global__ void softmax_small(const float* __restrict__ in, float* __restrict__ out, int n) {
    __shared__ float sm[64];
    int r = blockIdx.x, tid = threadIdx.x;
    float v = (tid < n) ? in[(size_t)r * n + tid] : -1e30f;
    sm[tid] = v; __syncthreads();
    for (int st = 32; st > 0; st >>= 1) {
        if (tid < st) sm[tid] = fmaxf(sm[tid], sm[tid + st]);
        __syncthreads();
    }
    float mx = sm[0]; __syncthreads();
    float e = (tid < n) ? expf(v - mx) : 0.f;
    sm[tid] = e; __syncthreads();
    for (int st = 32; st > 0; st >>= 1) {
        if (tid < st) sm[tid] += sm[tid + st];
        __syncthreads();
    }
    if (tid < n) out[(size_t)r * n + tid] = e / sm[0];
}

// ---------------- question feature + signed copies ----------------
__global__ void qfeat_k(const int* __restrict__ s1q, const int* __restrict__ s2q) {
    int b = blockIdx.x, g = blockIdx.y;
    __shared__ float att[TT];
    if (threadIdx.x < TT) att[threadIdx.x] = g_qatt[(b * 2 + g) * TT + threadIdx.x];
    __syncthreads();
    for (int h = threadIdx.x; h < HH; h += blockDim.x) {
        float acc = 0.f;
        for (int t = 0; t < TT; t++)
            acc += att[t] * g_hs[((size_t)t * BB + b) * HH + h];
        int j = g * HH + h;
        g_qfeat[b * QDIM + j] = acc;
        g_qv1[b * QDIM + j] = acc * (float)(2 * s1q[j] - 1);
        g_qv2[b * QDIM + j] = acc * (float)(2 * s2q[j] - 1);
    }
}

// ---------------- MCB1: scatter, pool ----------------
__global__ void scatter1(const float* __restrict__ img, const int* __restrict__ h1x,
                         const int* __restrict__ s1x) {
    int id = blockIdx.x * 256 + threadIdx.x;
    if (id >= BB * SS * FEATN) return;
    int f = id % FEATN;
    int r = id / FEATN;
    int s = r % SS, b = r / SS;
    int n = f * SS + s;
    float v = img[id] * (float)(2 * s1x[n] - 1);
    atomicAdd(&g_csx[(size_t)b * D1N + h1x[n]], v);
}

__global__ void pool1() {
    int id = blockIdx.x * 256 + threadIdx.x;
    if (id >= BB * D1N) return;
    int t = id % D1N; int b = id / D1N;
    const float* cs = g_csx + (size_t)b * D1N;
    float a = 0.f;
#pragma unroll
    for (int f = 0; f < 5; f++) {
        int tt = t + 49 * f;
        if (tt >= D1N) tt -= D1N;
        a += cs[tt];
    }
    g_P1[id] = a;
}

// ---------------- MCB1 conv: smem window, j-quad inner, fused |x| partial ----------------
__global__ void conv1_k() {
    extern __shared__ float smw[];
    float* win = smw;                    // [WSZ]
    float* sq  = smw + WSZ;              // [JPAD]
    int*   sh  = (int*)(sq + JPAD);      // [JPAD]
    int b = blockIdx.y;
    int m0 = blockIdx.x * MTILE;
    int tid = threadIdx.x;

    for (int i = tid; i < JPAD; i += CTHREADS) {
        sq[i] = g_qp1[b * JPAD + i];
        sh[i] = g_hperm[i];
    }

    int mg = tid >> 6;
    int sl = tid & 63;
    bool lane_ok = sl < 49;
    int offb = 245 * mg + sl;
    float acc[7] = {0.f, 0.f, 0.f, 0.f, 0.f, 0.f, 0.f};
    const float* Pb = g_P1 + (size_t)b * D1N;
    int T0 = 245 * m0;

    for (int k = 0; k < NBINS; k++) {
        __syncthreads();
        int W0 = T0 - (k + 1) * BIN1 + 1;
        W0 %= D1N; if (W0 < 0) W0 += D1N;
        for (int i = tid; i < WSZ; i += CTHREADS) {
            int g = W0 + i; if (g >= D1N) g -= D1N;
            win[i] = Pb[g];
        }
        __syncthreads();
        int j0 = g_binoff[k], j1 = g_binoff[k + 1];
        if (lane_ok) {
            int base0 = (k + 1) * BIN1 - 1 + offb;
            for (int j = j0; j < j1; j += 4) {
                float4 q4 = *(const float4*)&sq[j];
                int4   h4 = *(const int4*)&sh[j];
                {
                    int a = base0 - h4.x; float q = q4.x;
#pragma unroll
                    for (int it = 0; it < 7; it++) acc[it] += q * win[a + 2450 * it];
                }
                {
                    int a = base0 - h4.y; float q = q4.y;
#pragma unroll
                    for (int it = 0; it < 7; it++) acc[it] += q * win[a + 2450 * it];
                }
                {
                    int a = base0 - h4.z; float q = q4.z;
#pragma unroll
                    for (int it = 0; it < 7; it++) acc[it] += q * win[a + 2450 * it];
                }
                {
                    int a = base0 - h4.w; float q = q4.w;
#pragma unroll
                    for (int it = 0; it < 7; it++) acc[it] += q * win[a + 2450 * it];
                }
            }
        }
    }

    // write + fused |x| partial for the L2 norm (||signed_sqrt(x)||^2 = sum|x|)
    float part = 0.f;
    if (lane_ok) {
#pragma unroll
        for (int it = 0; it < 7; it++) {
            int m = mg + 10 * it;
            if (m < MTILE && m0 + m < MON) {
                g_iq[(size_t)b * IQN + (m0 + m) * 49 + sl] = acc[it];
                part += fabsf(acc[it]);
            }
        }
    }
    __syncthreads();
    sq[tid] = part;
    __syncthreads();
    for (int st = 512; st > 0; st >>= 1) {
        if (tid < st && tid + st < CTHREADS) sq[tid] += sq[tid + st];
        __syncthreads();
    }
    if (tid == 0) atomicAdd(&g_nrm1[b], sq[0]);
}

__global__ void scale1_k() {
    int id = blockIdx.x * 256 + threadIdx.x;
    if (id >= BB * IQN) return;
    int b = id / IQN;
    float inv = 1.f / fmaxf(sqrtf(g_nrm1[b]), 1e-12f);
    float x = g_iq[id];
    g_iqn[id] = copysignf(sqrtf(fabsf(x)), x) * inv;
}

// ---------------- image feature ----------------
__global__ void ifeat_k(const float* __restrict__ img) {
    int b = blockIdx.x;
    __shared__ float a0[SS], a1[SS];
    if (threadIdx.x < SS) {
        a0[threadIdx.x] = g_iatt[(b * 2 + 0) * SS + threadIdx.x];
        a1[threadIdx.x] = g_iatt[(b * 2 + 1) * SS + threadIdx.x];
    }
    __syncthreads();
    int f = blockIdx.y * 256 + threadIdx.x;
    float acc0 = 0.f, acc1 = 0.f;
    for (int s = 0; s < SS; s++) {
        float v = img[((size_t)b * SS + s) * FEATN + f];
        acc0 += a0[s] * v; acc1 += a1[s] * v;
    }
    g_ifeat[b * IDIM + f] = acc0;
    g_ifeat[b * IDIM + FEATN + f] = acc1;
}

// ---------------- MCB2 fully fused ----------------
__global__ void mcb2_k(const int* __restrict__ h2i, const int* __restrict__ s2i,
                       const int* __restrict__ h2q) {
    __shared__ float cs[D2N];
    __shared__ float sq[QDIM];
    __shared__ int   shh[QDIM];
    __shared__ float red[256];
    int b = blockIdx.x, tid = threadIdx.x;
    for (int i = tid; i < D2N; i += 256) cs[i] = 0.f;
    for (int j = tid; j < QDIM; j += 256) { sq[j] = g_qv2[b * QDIM + j]; shh[j] = h2q[j]; }
    __syncthreads();
    for (int n = tid; n < IDIM; n += 256) {
        float v = g_ifeat[b * IDIM + n] * (float)(2 * s2i[n] - 1);
        atomicAdd(&cs[h2i[n]], v);
    }
    __syncthreads();
    float p[20];
#pragma unroll
    for (int k = 0; k < 20; k++) {
        int t = tid + k * 256;
        float a = 0.f;
        if (t < D2N) {
#pragma unroll
            for (int f = 0; f < 5; f++) { int u = t + f; if (u >= D2N) u -= D2N; a += cs[u]; }
        }
        p[k] = a;
    }
    __syncthreads();
#pragma unroll
    for (int k = 0; k < 20; k++) { int t = tid + k * 256; if (t < D2N) cs[t] = p[k]; }
    __syncthreads();
    float z[4] = {0.f, 0.f, 0.f, 0.f};
    int mb[4];
#pragma unroll
    for (int k = 0; k < 4; k++) { int m = tid + k * 256; mb[k] = (m < MON) ? 5 * m : 0; }
    for (int j = 0; j < QDIM; j++) {
        int h = shh[j]; float q = sq[j];
#pragma unroll
        for (int k = 0; k < 4; k++) { int d = mb[k] - h; if (d < 0) d += D2N; z[k] += q * cs[d]; }
    }
    float sa = 0.f;
#pragma unroll
    for (int k = 0; k < 4; k++) { if (tid + k * 256 < MON) sa += fabsf(z[k]); }
    red[tid] = sa; __syncthreads();
    for (int st = 128; st > 0; st >>= 1) {
        if (tid < st) red[tid] += red[tid + st];
        __syncthreads();
    }
    float inv = 1.f / fmaxf(sqrtf(red[0]), 1e-12f);
#pragma unroll
    for (int k = 0; k < 4; k++) {
        int m = tid + k * 256;
        if (m < MON) g_z2n[b * MON + m] = copysignf(sqrtf(fabsf(z[k])), z[k]) * inv;
    }
}

// ---------------- final softmax (3000) ----------------
__global__ void softmax_out(float* __restrict__ out) {
    int b = blockIdx.x, tid = threadIdx.x;
    __shared__ float red[256];
    const float* lg = g_logits + (size_t)b * VOCABN;
    float mx = -1e30f;
    for (int i = tid; i < VOCABN; i += 256) mx = fmaxf(mx, lg[i]);
    red[tid] = mx; __syncthreads();
    for (int st = 128; st > 0; st >>= 1) {
        if (tid < st) red[tid] = fmaxf(red[tid], red[tid + st]);
        __syncthreads();
    }
    mx = red[0]; __syncthreads();
    float s = 0.f;
    for (int i = tid; i < VOCABN; i += 256) s += expf(lg[i] - mx);
    red[tid] = s; __syncthreads();
    for (int st = 128; st > 0; st >>= 1) {
        if (tid < st) red[tid] += red[tid + st];
        __syncthreads();
    }
    float inv = 1.f / red[0];
    for (int i = tid; i < VOCABN; i += 256) out[(size_t)b * VOCABN + i] = expf(lg[i] - mx) * inv;
}

// ---------------- host launcher ----------------
static float* sym(const void* s) {
    void* p = nullptr;
    cudaGetSymbolAddress(&p, s);
    return (float*)p;
}

extern "C" void kernel_launch(void* const* d_in, const int* in_sizes, int n_in,
                              void* d_out, int out_size) {
    const float* ques  = (const float*)d_in[0];
    const float* img   = (const float*)d_in[1];
    const float* W_ih  = (const float*)d_in[2];
    const float* W_hh  = (const float*)d_in[3];
    const float* b_ih  = (const float*)d_in[4];
    const float* b_hh  = (const float*)d_in[5];
    const float* Wq1   = (const float*)d_in[6];
    const float* bq1   = (const float*)d_in[7];
    const float* Wq2   = (const float*)d_in[8];
    const float* bq2   = (const float*)d_in[9];
    const float* Wi1   = (const float*)d_in[10];
    const float* bi1   = (const float*)d_in[11];
    const float* Wi2   = (const float*)d_in[12];
    const float* bi2   = (const float*)d_in[13];
    const float* Wp    = (const float*)d_in[14];
    const float* bp    = (const float*)d_in[15];
    const int* h1x = (const int*)d_in[16];
    const int* s1x = (const int*)d_in[17];
    const int* h1q = (const int*)d_in[18];
    const int* s1q = (const int*)d_in[19];
    const int* h2i = (const int*)d_in[20];
    const int* s2i = (const int*)d_in[21];
    const int* h2q = (const int*)d_in[22];
    const int* s2q = (const int*)d_in[23];
    float* out = (float*)d_out;

    float* p_xW    = sym(g_xW);
    float* p_hs    = sym(g_hs);
    float* p_qa1   = sym(g_qa1);
    float* p_qa2   = sym(g_qa2);
    float* p_qatt  = sym(g_qatt);
    float* p_ia1   = sym(g_ia1);
    float* p_ia2   = sym(g_ia2);
    float* p_iatt  = sym(g_iatt);
    float* p_iqn   = sym(g_iqn);
    float* p_z2n   = sym(g_z2n);
    float* p_logits= sym(g_logits);

    cudaFuncSetAttribute(conv1_k, cudaFuncAttributeMaxDynamicSharedMemorySize, CONV_SMEM);

    cudaStream_t side;
    cudaStreamCreateWithFlags(&side, cudaStreamNonBlocking);
    cudaEvent_t e_fork, e_join;
    cudaEventCreateWithFlags(&e_fork, cudaEventDisableTiming);
    cudaEventCreateWithFlags(&e_join, cudaEventDisableTiming);

    // main-stream init needed by both branches
    init_state_k<<<(BB*HH + 255)/256, 256>>>();
    bin_h_k<<<1, 256>>>(h1q);

    // fork: img-side preprocessing on side stream
    cudaEventRecord(e_fork, 0);
    cudaStreamWaitEvent(side, e_fork, 0);
    zero_csx_k<<<(BB*D1N + 255)/256, 256, 0, side>>>();
    scatter1<<<(BB*SS*FEATN + 255)/256, 256, 0, side>>>(img, h1x, s1x);
    pool1<<<(BB*D1N + 255)/256, 256, 0, side>>>();
    cudaEventRecord(e_join, side);

    // main stream: xW GEMM + LSTM chain
    {
        dim3 g(G4/64, (TT*BB + 63)/64, 1);
        sgemm<<<g, 256>>>(ques, W_ih, b_ih, b_hh, p_xW,
                          TT*BB, G4, EE, BB, EE, TT*EE, 1, 0);
    }
    for (int t = 0; t < TT; t++) {
        dim3 g(64, 4, 1);
        lstm_fused<<<g, 256>>>(W_hh, t);
    }

    // question attention
    {
        dim3 g(512/64, (TT*BB + 63)/64, 1);
        sgemm<<<g, 256>>>(p_hs, Wq1, bq1, nullptr, p_qa1,
                          TT*BB, 512, HH, 1, HH, 0, 1, 1);
    }
    att2_k<<<TT*BB, 128>>>(p_qa1, Wq2, bq2, p_qa2, TT, 0);
    softmax_small<<<BB*2, 64>>>(p_qa2, p_qatt, TT);
    {
        dim3 g(BB, 2);
        qfeat_k<<<g, 256>>>(s1q, s2q);
    }
    permq_k<<<BB, 256>>>();

    // join: conv1 needs pool1 (side) + permq (main)
    cudaStreamWaitEvent(0, e_join, 0);

    // MCB1 conv (fused norm partial) + scale
    {
        dim3 g((MON + MTILE - 1)/MTILE, BB);
        conv1_k<<<g, CTHREADS, CONV_SMEM>>>();
    }
    scale1_k<<<(BB*IQN + 255)/256, 256>>>();

    // image attention
    {
        dim3 g(512/64, (BB*SS + 63)/64, 1);
        sgemm<<<g, 256>>>(p_iqn, Wi1, bi1, nullptr, p_ia1,
                          BB*SS, 512, MON, SS, IQN, 1, SS, 1);
    }
    att2_k<<<BB*SS, 128>>>(p_ia1, Wi2, bi2, p_ia2, SS, 1);
    softmax_small<<<BB*2, 64>>>(p_ia2, p_iatt, SS);
    {
        dim3 g(BB, FEATN/256);
        ifeat_k<<<g, 256>>>(img);
    }

    // MCB2 fused
    mcb2_k<<<BB, 256>>>(h2i, s2i, h2q);

    // classifier + softmax
    {
        dim3 g((VOCABN + 63)/64, 1, 1);
        sgemm<<<g, 256>>>(p_z2n, Wp, bp, nullptr, p_logits,
                          BB, VOCABN, MON, 1, MON, 0, 1, 0);
    }
    softmax_out<<<BB, 256>>>(out);
}